// round 10
// baseline (speedup 1.0000x reference)
#include <cuda_runtime.h>
#include <cuda_bf16.h>
#include <math.h>
#include <stdint.h>

#define D 128
#define MAXN 50000
#define PMAXN (MAXN + 128)          // padded rows for tail-tile cp.async
#define MAXE 800000

// ---------------- scratch ----------------
__device__ float    g_H [MAXN * D];            // fp32 features for gather
__device__ uint32_t g_XHh[PMAXN * 64];         // x planes (L1) / HM planes (L2)
__device__ uint32_t g_XHl[PMAXN * 64];
__device__ uint32_t g_A1h[PMAXN * 64];
__device__ uint32_t g_A1l[PMAXN * 64];
__device__ uint32_t g_A2h[PMAXN * 64];
__device__ uint32_t g_A2l[PMAXN * 64];
__device__ int   g_degF[MAXN];
__device__ int   g_degR[MAXN];
__device__ int   g_offF[MAXN];
__device__ int   g_offR[MAXN];
__device__ int   g_curF[MAXN];
__device__ int   g_curR[MAXN];
__device__ float g_dF[MAXN];
__device__ float g_dR[MAXN];
__device__ int2  g_csrF[MAXE];
__device__ int2  g_csrR[MAXE];
#define WPN 8192
__device__ uint32_t g_Wp[12 * WPN];

__device__ __forceinline__ uint32_t pack_bf16(float lo_val, float hi_val) {
    uint32_t u;
    asm("cvt.rn.bf16x2.f32 %0, %1, %2;" : "=r"(u) : "f"(hi_val), "f"(lo_val));
    return u;
}
__device__ __forceinline__ float2 unpack_bf16(uint32_t u) {
    __nv_bfloat162 b = *(__nv_bfloat162*)&u;
    return __bfloat1622float2(b);   // {x=lo, y=hi}
}
__device__ __forceinline__ void mma16(float* d, uint32_t a0, uint32_t a1, uint32_t a2,
                                      uint32_t a3, uint32_t b0, uint32_t b1) {
    asm volatile("mma.sync.aligned.m16n8k16.row.col.f32.bf16.bf16.f32 "
                 "{%0,%1,%2,%3}, {%4,%5,%6,%7}, {%8,%9}, {%0,%1,%2,%3};"
                 : "+f"(d[0]), "+f"(d[1]), "+f"(d[2]), "+f"(d[3])
                 : "r"(a0), "r"(a1), "r"(a2), "r"(a3), "r"(b0), "r"(b1));
}
__device__ __forceinline__ void cpa16(uint32_t dst, const void* src) {
    asm volatile("cp.async.cg.shared.global [%0], [%1], 16;" :: "r"(dst), "l"(src));
}
__device__ __forceinline__ void cpa_commit() {
    asm volatile("cp.async.commit_group;" ::: "memory");
}
__device__ __forceinline__ void cpa_wait0() {
    asm volatile("cp.async.wait_group 0;" ::: "memory");
}
// plane destination index for (row, pair p)
__device__ __forceinline__ int plane_idx(int row, int p) {
    int X = ((row >> 1) & 3) << 2;
    return row * 64 + ((p & ~15) | ((p & 15) ^ X));
}

// ---------------- launch 1: zero deg + weight planes + x planes ----------------
__global__ void zw_kernel(int* dgF, int* dgR, int n,
                          const float* __restrict__ W1, const float* __restrict__ W2,
                          const float* __restrict__ w11, const float* __restrict__ w12,
                          const float* __restrict__ w21, const float* __restrict__ w22,
                          uint32_t* Wp, const float* __restrict__ x,
                          uint32_t* XPh, uint32_t* XPl) {
    int i = blockIdx.x * blockDim.x + threadIdx.x;
    if (i < n) { dgF[i] = 0; dgR[i] = 0; }
    if (i < WPN) {
        int row = i >> 6;
        int p   = i & 63;
        int k0  = 2 * p, k1 = 2 * p + 1;
        int dst = plane_idx(row, p);
        const float* srcs[6];
        srcs[0] = W1; srcs[1] = W2; srcs[2] = w11; srcs[3] = w12; srcs[4] = w21; srcs[5] = w22;
#pragma unroll
        for (int wgt = 0; wgt < 6; wgt++) {
            float v0, v1;
            if (wgt < 2) {              // transpose [K,N] -> [N,K]
                v0 = srcs[wgt][k0 * D + row];
                v1 = srcs[wgt][k1 * D + row];
            } else {
                v0 = srcs[wgt][row * D + k0];
                v1 = srcs[wgt][row * D + k1];
            }
            float h0 = __bfloat162float(__float2bfloat16_rn(v0));
            float h1 = __bfloat162float(__float2bfloat16_rn(v1));
            Wp[(2 * wgt + 0) * WPN + dst] = pack_bf16(v0, v1);
            Wp[(2 * wgt + 1) * WPN + dst] = pack_bf16(v0 - h0, v1 - h1);
        }
    }
    if (i < n * 64) {
        float2 v = ((const float2*)x)[i];
        int row = i >> 6, p = i & 63;
        int dst = plane_idx(row, p);
        float h0 = __bfloat162float(__float2bfloat16_rn(v.x));
        float h1 = __bfloat162float(__float2bfloat16_rn(v.y));
        XPh[dst] = pack_bf16(v.x, v.y);
        XPl[dst] = pack_bf16(v.x - h0, v.y - h1);
    }
}

// ---------------- launch 2: degree histogram ----------------
__global__ void deg_kernel(const int* __restrict__ ei, int E, int* dgF, int* dgR) {
    int e = blockIdx.x * blockDim.x + threadIdx.x;
    if (e < E) {
        atomicAdd(dgF + ei[E + e], 1);
        atomicAdd(dgR + ei[e],     1);
    }
}

// ---------------- launch 3: merged exclusive scan + dinv -------------------
__global__ void scan_kernel(const int* __restrict__ degF, const int* __restrict__ degR,
                            int* offF, int* offR, int* curF, int* curR,
                            float* dF, float* dR, int n) {
    __shared__ int sF[32], sR[32];
    __shared__ int baseF, baseR;
    int b = blockIdx.x, t = threadIdx.x, lane = t & 31, w = t >> 5;

    int aF = 0, aR = 0;
    int lim = b * 1024;
    for (int i = t; i < lim; i += 1024) { aF += degF[i]; aR += degR[i]; }
#pragma unroll
    for (int o = 16; o; o >>= 1) {
        aF += __shfl_down_sync(0xffffffffu, aF, o);
        aR += __shfl_down_sync(0xffffffffu, aR, o);
    }
    if (lane == 0) { sF[w] = aF; sR[w] = aR; }
    __syncthreads();
    if (w == 0) {
        aF = sF[lane]; aR = sR[lane];
#pragma unroll
        for (int o = 16; o; o >>= 1) {
            aF += __shfl_down_sync(0xffffffffu, aF, o);
            aR += __shfl_down_sync(0xffffffffu, aR, o);
        }
        if (lane == 0) { baseF = aF; baseR = aR; }
    }
    __syncthreads();

    int i = b * 1024 + t;
    int vF = (i < n) ? degF[i] : 0;
    int vR = (i < n) ? degR[i] : 0;
    int iF = vF, iR = vR;
#pragma unroll
    for (int o = 1; o < 32; o <<= 1) {
        int a = __shfl_up_sync(0xffffffffu, iF, o);
        int c = __shfl_up_sync(0xffffffffu, iR, o);
        if (lane >= o) { iF += a; iR += c; }
    }
    __syncthreads();
    if (lane == 31) { sF[w] = iF; sR[w] = iR; }
    __syncthreads();
    if (w == 0) {
        int aF2 = sF[lane], aR2 = sR[lane];
#pragma unroll
        for (int o = 1; o < 32; o <<= 1) {
            int a = __shfl_up_sync(0xffffffffu, aF2, o);
            int c = __shfl_up_sync(0xffffffffu, aR2, o);
            if (lane >= o) { aF2 += a; aR2 += c; }
        }
        sF[lane] = aF2; sR[lane] = aR2;
    }
    __syncthreads();
    int pF = (w > 0) ? sF[w - 1] : 0;
    int pR = (w > 0) ? sR[w - 1] : 0;
    if (i < n) {
        int exF = baseF + pF + iF - vF;
        int exR = baseR + pR + iR - vR;
        offF[i] = exF; offR[i] = exR;
        curF[i] = exF; curR[i] = exR;
        dF[i] = rsqrtf((float)vF + 1.f);
        dR[i] = rsqrtf((float)vR + 1.f);
    }
}

// ---------------- launch 5: fill CSR lists ----------------
__global__ void fill_csr_kernel(const int* __restrict__ ei, int E,
                                const float* __restrict__ dF, const float* __restrict__ dR,
                                int* curF, int* curR, int2* csrF, int2* csrR) {
    int e = blockIdx.x * blockDim.x + threadIdx.x;
    if (e >= E) return;
    int s = ei[e];
    int d = ei[E + e];
    float cf = dF[s] * dF[d];
    float cr = dR[s] * dR[d];
    int pF = atomicAdd(curF + d, 1);
    csrF[pF] = make_int2(s, __float_as_int(cf));
    int pR = atomicAdd(curR + s, 1);
    csrR[pR] = make_int2(d, __float_as_int(cr));
}

// ---------------- bf16x3 pipelined GEMM (cp.async double buffer) ----------------
// All A operands are pre-swizzled hi/lo pair planes. 128x128 tile, 256 thr, 2 CTA/SM.
// GATE=0: Cf[M,128] = A @ B1^T (fp32 out)
// GATE=1: gated combine; OUTP=1 -> plane output (Ch/Cl), OUTP=0 -> fp32 (Cf)
template<int GATE, int OUTP>
__global__ void __launch_bounds__(256, 2)
mma_gemm(const uint32_t* __restrict__ Aah, const uint32_t* __restrict__ Aal,
         const uint32_t* __restrict__ Abh, const uint32_t* __restrict__ Abl,
         const uint32_t* __restrict__ B1h, const uint32_t* __restrict__ B1l,
         const uint32_t* __restrict__ B2h, const uint32_t* __restrict__ B2l,
         const float* __restrict__ bias,
         float* __restrict__ Cf, uint32_t* __restrict__ Ch, uint32_t* __restrict__ Cl,
         int M) {
    extern __shared__ uint32_t sm[];    // 2 stages x 4 planes x 2048 words = 64 KB
    const uint32_t smbase = (uint32_t)__cvta_generic_to_shared(sm);

    const int tid  = threadIdx.x;
    const int wid  = tid >> 5;
    const int lane = tid & 31;
    const int g    = lane >> 2;
    const int c    = lane & 3;
    const int wm   = wid & 3;
    const int wn   = wid >> 2;
    const int m0   = blockIdx.x * 128;

    float acc[2][8][4];
#pragma unroll
    for (int mt = 0; mt < 2; mt++)
#pragma unroll
        for (int nt = 0; nt < 8; nt++)
#pragma unroll
            for (int r = 0; r < 4; r++) acc[mt][nt][r] = 0.f;

    const int r0 = wm * 32 + g;
    const int nr = wn * 64 + g;
    const int NCH = GATE ? 8 : 4;

    // prefetch helper (macro-ish lambda)
    auto prefetch = [&](int stage, int ch) {
        const uint32_t* Ah = (GATE && ch >= 4) ? Abh : Aah;
        const uint32_t* Al = (GATE && ch >= 4) ? Abl : Aal;
        const uint32_t* Bh = (GATE && ch >= 4) ? B2h : B1h;
        const uint32_t* Bl = (GATE && ch >= 4) ? B2l : B1l;
        const int kcp = (ch & 3) * 16;
        const uint32_t sbase = smbase + (uint32_t)(stage * 8192) * 4u;
#pragma unroll
        for (int i = 0; i < 8; i++) {
            int q = i * 256 + tid;
            int L = q & 511;
            int row = L >> 2, seg = L & 3;
            const uint32_t* src;
            switch (i >> 1) {
                case 0: src = Ah; break;
                case 1: src = Al; break;
                case 2: src = Bh; break;
                default: src = Bl; break;
            }
            // A planes indexed by tile row (m0+row); B planes by absolute row
            int grow = (i < 4) ? (m0 + row) : row;
            cpa16(sbase + (uint32_t)(((i >> 1) << 11) + row * 16 + seg * 4) * 4u,
                  src + grow * 64 + kcp + seg * 4);
        }
        cpa_commit();
    };

    prefetch(0, 0);
    for (int ch = 0; ch < NCH; ch++) {
        const int stg = (ch & 1) * 8192;
        cpa_wait0();
        __syncthreads();
        if (ch + 1 < NCH) prefetch((ch + 1) & 1, ch + 1);
#pragma unroll
        for (int ks = 0; ks < 2; ks++) {
            const int pc = ks * 8;
            uint32_t aH[2][4], aL[2][4];
#pragma unroll
            for (int mt = 0; mt < 2; mt++) {
                int ra = r0 + mt * 16;
                int rb = ra + 8;
                int Xa = ((ra >> 1) & 3) << 2;
                int Xb = ((rb >> 1) & 3) << 2;
                int ia0 = stg + ra * 16 + ((pc + c) ^ Xa);
                int ib0 = stg + rb * 16 + ((pc + c) ^ Xb);
                int ia1 = stg + ra * 16 + ((pc + c + 4) ^ Xa);
                int ib1 = stg + rb * 16 + ((pc + c + 4) ^ Xb);
                aH[mt][0] = sm[ia0];        aH[mt][1] = sm[ib0];
                aH[mt][2] = sm[ia1];        aH[mt][3] = sm[ib1];
                aL[mt][0] = sm[2048 + ia0]; aL[mt][1] = sm[2048 + ib0];
                aL[mt][2] = sm[2048 + ia1]; aL[mt][3] = sm[2048 + ib1];
            }
#pragma unroll
            for (int nt = 0; nt < 8; nt++) {
                int n  = nr + nt * 8;
                int Xn = ((n >> 1) & 3) << 2;
                int i0 = stg + n * 16 + ((pc + c) ^ Xn);
                int i1 = stg + n * 16 + ((pc + c + 4) ^ Xn);
                uint32_t bh0 = sm[4096 + i0], bh1 = sm[4096 + i1];
                uint32_t bl0 = sm[6144 + i0], bl1 = sm[6144 + i1];
#pragma unroll
                for (int mt = 0; mt < 2; mt++) {
                    mma16(acc[mt][nt], aH[mt][0], aH[mt][1], aH[mt][2], aH[mt][3], bh0, bh1);
                    mma16(acc[mt][nt], aL[mt][0], aL[mt][1], aL[mt][2], aL[mt][3], bh0, bh1);
                    mma16(acc[mt][nt], aH[mt][0], aH[mt][1], aH[mt][2], aH[mt][3], bl0, bl1);
                }
            }
        }
        __syncthreads();   // all warps done reading stage before next prefetch reuses it
    }

    // epilogue
#pragma unroll
    for (int mt = 0; mt < 2; mt++) {
#pragma unroll
        for (int rh = 0; rh < 2; rh++) {
            int row = m0 + wm * 32 + mt * 16 + g + rh * 8;
            if (row >= M) continue;
#pragma unroll
            for (int nt = 0; nt < 8; nt++) {
                int col = wn * 64 + nt * 8 + c * 2;
                float v0 = acc[mt][nt][rh * 2 + 0];
                float v1 = acc[mt][nt][rh * 2 + 1];
                if (!GATE) {
                    *(float2*)(Cf + (size_t)row * D + col) = make_float2(v0, v1);
                } else {
                    int dp = plane_idx(row, col >> 1);
                    float2 bb = *(const float2*)(bias + col);
                    float2 h1 = unpack_bf16(Aah[dp]), l1 = unpack_bf16(Aal[dp]);
                    float2 h2 = unpack_bf16(Abh[dp]), l2 = unpack_bf16(Abl[dp]);
                    float o1x = h1.x + l1.x, o1y = h1.y + l1.y;
                    float o2x = h2.x + l2.x, o2y = h2.y + l2.y;
                    float g0 = 1.f / (1.f + __expf(-(v0 + bb.x)));
                    float g1 = 1.f / (1.f + __expf(-(v1 + bb.y)));
                    float ox = g0 * o1x + (1.f - g0) * o2x;
                    float oy = g1 * o1y + (1.f - g1) * o2y;
                    if (OUTP) {
                        float hx = __bfloat162float(__float2bfloat16_rn(ox));
                        float hy = __bfloat162float(__float2bfloat16_rn(oy));
                        Ch[dp] = pack_bf16(ox, oy);
                        Cl[dp] = pack_bf16(ox - hx, oy - hy);
                    } else {
                        *(float2*)(Cf + (size_t)row * D + col) = make_float2(ox, oy);
                    }
                }
            }
        }
    }
}

// ---------------- gather: warp/node, 4-way unrolled, plane outputs ---------------
__global__ void gather_kernel(const float* __restrict__ H,
                              const int2* __restrict__ csrF, const int2* __restrict__ csrR,
                              const int* __restrict__ offF, const int* __restrict__ offR,
                              const int* __restrict__ degF, const int* __restrict__ degR,
                              const float* __restrict__ dF, const float* __restrict__ dR,
                              const float* __restrict__ bias,
                              uint32_t* __restrict__ A1h, uint32_t* __restrict__ A1l,
                              uint32_t* __restrict__ A2h, uint32_t* __restrict__ A2l,
                              int N) {
    int w = (blockIdx.x * blockDim.x + threadIdx.x) >> 5;
    int lane = threadIdx.x & 31;
    if (w >= N) return;
    const float4* H4 = (const float4*)H;

    float4 acc1 = make_float4(0.f, 0.f, 0.f, 0.f);
    float4 acc2 = make_float4(0.f, 0.f, 0.f, 0.f);

#pragma unroll 2
    for (int dir = 0; dir < 2; dir++) {
        const int2* csr = dir ? csrR : csrF;
        int off = dir ? offR[w] : offF[w];
        int nE  = dir ? degR[w] : degF[w];
        float4* pacc = dir ? &acc2 : &acc1;
        float4 a = *pacc;
        for (int b = 0; b < nE; b += 32) {
            int m = min(32, nE - b);
            int2 ent = (lane < m) ? csr[off + b + lane] : make_int2(0, 0);
            int j = 0;
            for (; j + 3 < m; j += 4) {
                int   i0 = __shfl_sync(0xffffffffu, ent.x, j);
                float c0 = __int_as_float(__shfl_sync(0xffffffffu, ent.y, j));
                int   i1 = __shfl_sync(0xffffffffu, ent.x, j + 1);
                float c1 = __int_as_float(__shfl_sync(0xffffffffu, ent.y, j + 1));
                int   i2 = __shfl_sync(0xffffffffu, ent.x, j + 2);
                float c2 = __int_as_float(__shfl_sync(0xffffffffu, ent.y, j + 2));
                int   i3 = __shfl_sync(0xffffffffu, ent.x, j + 3);
                float c3 = __int_as_float(__shfl_sync(0xffffffffu, ent.y, j + 3));
                float4 h0 = H4[i0 * 32 + lane];
                float4 h1 = H4[i1 * 32 + lane];
                float4 h2 = H4[i2 * 32 + lane];
                float4 h3 = H4[i3 * 32 + lane];
                a.x = fmaf(h0.x, c0, a.x); a.y = fmaf(h0.y, c0, a.y);
                a.z = fmaf(h0.z, c0, a.z); a.w = fmaf(h0.w, c0, a.w);
                a.x = fmaf(h1.x, c1, a.x); a.y = fmaf(h1.y, c1, a.y);
                a.z = fmaf(h1.z, c1, a.z); a.w = fmaf(h1.w, c1, a.w);
                a.x = fmaf(h2.x, c2, a.x); a.y = fmaf(h2.y, c2, a.y);
                a.z = fmaf(h2.z, c2, a.z); a.w = fmaf(h2.w, c2, a.w);
                a.x = fmaf(h3.x, c3, a.x); a.y = fmaf(h3.y, c3, a.y);
                a.z = fmaf(h3.z, c3, a.z); a.w = fmaf(h3.w, c3, a.w);
            }
            for (; j < m; j++) {
                int   i0 = __shfl_sync(0xffffffffu, ent.x, j);
                float c0 = __int_as_float(__shfl_sync(0xffffffffu, ent.y, j));
                float4 h0 = H4[i0 * 32 + lane];
                a.x = fmaf(h0.x, c0, a.x); a.y = fmaf(h0.y, c0, a.y);
                a.z = fmaf(h0.z, c0, a.z); a.w = fmaf(h0.w, c0, a.w);
            }
        }
        *pacc = a;
    }

    float4 hn = H4[w * 32 + lane];
    float4 bb = ((const float4*)bias)[lane];
    float f2 = dF[w]; f2 *= f2;
    float r2 = dR[w]; r2 *= r2;
    float4 a1, a2;
    a1.x = fmaxf(fmaf(hn.x, f2, acc1.x) + bb.x, 0.f);
    a1.y = fmaxf(fmaf(hn.y, f2, acc1.y) + bb.y, 0.f);
    a1.z = fmaxf(fmaf(hn.z, f2, acc1.z) + bb.z, 0.f);
    a1.w = fmaxf(fmaf(hn.w, f2, acc1.w) + bb.w, 0.f);
    a2.x = fmaxf(fmaf(hn.x, r2, acc2.x) + bb.x, 0.f);
    a2.y = fmaxf(fmaf(hn.y, r2, acc2.y) + bb.y, 0.f);
    a2.z = fmaxf(fmaf(hn.z, r2, acc2.z) + bb.z, 0.f);
    a2.w = fmaxf(fmaf(hn.w, r2, acc2.w) + bb.w, 0.f);

    // write plane outputs: pairs p0=2*lane, p0+1 (uint2-aligned after swizzle)
    int dst = plane_idx(w, 2 * lane);
    {
        float hx = __bfloat162float(__float2bfloat16_rn(a1.x));
        float hy = __bfloat162float(__float2bfloat16_rn(a1.y));
        float hz = __bfloat162float(__float2bfloat16_rn(a1.z));
        float hw = __bfloat162float(__float2bfloat16_rn(a1.w));
        *(uint2*)&A1h[dst] = make_uint2(pack_bf16(a1.x, a1.y), pack_bf16(a1.z, a1.w));
        *(uint2*)&A1l[dst] = make_uint2(pack_bf16(a1.x - hx, a1.y - hy),
                                        pack_bf16(a1.z - hz, a1.w - hw));
    }
    {
        float hx = __bfloat162float(__float2bfloat16_rn(a2.x));
        float hy = __bfloat162float(__float2bfloat16_rn(a2.y));
        float hz = __bfloat162float(__float2bfloat16_rn(a2.z));
        float hw = __bfloat162float(__float2bfloat16_rn(a2.w));
        *(uint2*)&A2h[dst] = make_uint2(pack_bf16(a2.x, a2.y), pack_bf16(a2.z, a2.w));
        *(uint2*)&A2l[dst] = make_uint2(pack_bf16(a2.x - hx, a2.y - hy),
                                        pack_bf16(a2.z - hz, a2.w - hw));
    }
}

// ---------------- driver ----------------
extern "C" void kernel_launch(void* const* d_in, const int* in_sizes, int n_in,
                              void* d_out, int out_size) {
    const float* x   = (const float*)d_in[0];
    const int*   ei  = (const int*)  d_in[1];
    const float* W1  = (const float*)d_in[2];
    const float* bc1 = (const float*)d_in[3];
    const float* W2  = (const float*)d_in[4];
    const float* bc2 = (const float*)d_in[5];
    const float* w11 = (const float*)d_in[6];
    const float* w12 = (const float*)d_in[7];
    const float* b1  = (const float*)d_in[8];
    const float* w21 = (const float*)d_in[9];
    const float* w22 = (const float*)d_in[10];
    const float* b2  = (const float*)d_in[11];

    const int N = in_sizes[0] / D;
    const int E = in_sizes[1] / 2;

    float *H, *dF, *dR;
    uint32_t *XHh, *XHl, *A1h, *A1l, *A2h, *A2l, *Wp;
    int *degF, *degR, *offF, *offR, *curF, *curR;
    int2 *csrF, *csrR;
    cudaGetSymbolAddress((void**)&H,    g_H);
    cudaGetSymbolAddress((void**)&XHh,  g_XHh);
    cudaGetSymbolAddress((void**)&XHl,  g_XHl);
    cudaGetSymbolAddress((void**)&A1h,  g_A1h);
    cudaGetSymbolAddress((void**)&A1l,  g_A1l);
    cudaGetSymbolAddress((void**)&A2h,  g_A2h);
    cudaGetSymbolAddress((void**)&A2l,  g_A2l);
    cudaGetSymbolAddress((void**)&degF, g_degF);
    cudaGetSymbolAddress((void**)&degR, g_degR);
    cudaGetSymbolAddress((void**)&offF, g_offF);
    cudaGetSymbolAddress((void**)&offR, g_offR);
    cudaGetSymbolAddress((void**)&curF, g_curF);
    cudaGetSymbolAddress((void**)&curR, g_curR);
    cudaGetSymbolAddress((void**)&dF,   g_dF);
    cudaGetSymbolAddress((void**)&dR,   g_dR);
    cudaGetSymbolAddress((void**)&csrF, g_csrF);
    cudaGetSymbolAddress((void**)&csrR, g_csrR);
    cudaGetSymbolAddress((void**)&Wp,   g_Wp);

    const uint32_t* W1h  = Wp + 0 * WPN;  const uint32_t* W1l  = Wp + 1 * WPN;
    const uint32_t* W2h  = Wp + 2 * WPN;  const uint32_t* W2l  = Wp + 3 * WPN;
    const uint32_t* G11h = Wp + 4 * WPN;  const uint32_t* G11l = Wp + 5 * WPN;
    const uint32_t* G12h = Wp + 6 * WPN;  const uint32_t* G12l = Wp + 7 * WPN;
    const uint32_t* G21h = Wp + 8 * WPN;  const uint32_t* G21l = Wp + 9 * WPN;
    const uint32_t* G22h = Wp + 10 * WPN; const uint32_t* G22l = Wp + 11 * WPN;

    const int SMEM = 65536;
    cudaFuncSetAttribute(mma_gemm<0,0>, cudaFuncAttributeMaxDynamicSharedMemorySize, SMEM);
    cudaFuncSetAttribute(mma_gemm<1,1>, cudaFuncAttributeMaxDynamicSharedMemorySize, SMEM);
    cudaFuncSetAttribute(mma_gemm<1,0>, cudaFuncAttributeMaxDynamicSharedMemorySize, SMEM);

    const int TB = 256;
    const int gZ    = (N * 64 + TB - 1) / TB;
    const int gE    = (E + TB - 1) / TB;
    const int gGath = (N * 32 + TB - 1) / TB;
    const int gMma  = (N + 127) / 128;
    const int nbs   = (N + 1023) / 1024;

    zw_kernel<<<gZ, TB>>>(degF, degR, N, W1, W2, w11, w12, w21, w22, Wp, x,
                          XHh, XHl);                                             // 1
    deg_kernel<<<gE, TB>>>(ei, E, degF, degR);                                   // 2
    scan_kernel<<<nbs, 1024>>>(degF, degR, offF, offR, curF, curR, dF, dR, N);   // 3
    mma_gemm<0,0><<<gMma, TB, SMEM>>>(XHh, XHl, nullptr, nullptr,
                                      W1h, W1l, nullptr, nullptr,
                                      nullptr, H, nullptr, nullptr, N);          // 4 PROFILED
    fill_csr_kernel<<<gE, TB>>>(ei, E, dF, dR, curF, curR, csrF, csrR);          // 5

    // ================= layer 1 =================
    gather_kernel<<<gGath, TB>>>(H, csrF, csrR, offF, offR, degF, degR,
                                 dF, dR, bc1, A1h, A1l, A2h, A2l, N);
    mma_gemm<1,1><<<gMma, TB, SMEM>>>(A1h, A1l, A2h, A2l,
                                      G11h, G11l, G12h, G12l,
                                      b1, nullptr, XHh, XHl, N);   // HM planes

    // ================= layer 2 =================
    mma_gemm<0,0><<<gMma, TB, SMEM>>>(XHh, XHl, nullptr, nullptr,
                                      W2h, W2l, nullptr, nullptr,
                                      nullptr, H, nullptr, nullptr, N);
    gather_kernel<<<gGath, TB>>>(H, csrF, csrR, offF, offR, degF, degR,
                                 dF, dR, bc2, A1h, A1l, A2h, A2l, N);
    mma_gemm<1,0><<<gMma, TB, SMEM>>>(A1h, A1l, A2h, A2l,
                                      G21h, G21l, G22h, G22l,
                                      b2, (float*)d_out, nullptr, nullptr, N);
}